// round 13
// baseline (speedup 1.0000x reference)
#include <cuda_runtime.h>
#include <cuda_fp16.h>
#include <cstdint>

// ---------------------------------------------------------------------------
// Swin block on GB300 (sm_103 plain target): fp16 mma.sync GEMMs (128x128 CTA
// tile, 8 warps of 64x32, k-chunk 64, 3-stage cp.async, single-barrier
// mainloop, 2 CTAs/SM); tensor-core windowed attention; fp32 LN/residual.
// ---------------------------------------------------------------------------

#define T_TOK   32768
#define C_DIM   512
#define QKVD    1536
#define MLPD    2048
#define HEADS_N 16

// ------------------------------- scratch -----------------------------------
__device__ float g_hid[(size_t)T_TOK * C_DIM];
__device__ float g_bqkv[QKVD];
__device__ __half h_xw  [(size_t)T_TOK * C_DIM];
__device__ __half h_qkv [(size_t)T_TOK * QKVD];
__device__ __half h_ctx [(size_t)T_TOK * C_DIM];
__device__ __half h_y   [(size_t)T_TOK * C_DIM];
__device__ __half h_h1  [(size_t)T_TOK * MLPD];
__device__ __half h_wqkvT[(size_t)QKVD * C_DIM];
__device__ __half h_woT [(size_t)C_DIM * C_DIM];
__device__ __half h_w1T [(size_t)MLPD * C_DIM];
__device__ __half h_w2T [(size_t)C_DIM * MLPD];

// ------------------------------- helpers -----------------------------------
__device__ __forceinline__ uint32_t smem_u32(const void* p) {
    uint32_t a;
    asm("{ .reg .u64 t; cvta.to.shared.u64 t, %1; cvt.u32.u64 %0, t; }"
        : "=r"(a) : "l"(p));
    return a;
}
__device__ __forceinline__ void cp_async16(uint32_t dst, const void* src) {
    asm volatile("cp.async.cg.shared.global [%0], [%1], 16;" :: "r"(dst), "l"(src));
}
__device__ __forceinline__ void cp_commit() { asm volatile("cp.async.commit_group;"); }
__device__ __forceinline__ void cp_wait1()  { asm volatile("cp.async.wait_group 1;" ::: "memory"); }

__device__ __forceinline__ void ldm_x4(uint32_t* r, uint32_t addr) {
    asm volatile("ldmatrix.sync.aligned.m8n8.x4.shared.b16 {%0,%1,%2,%3}, [%4];"
                 : "=r"(r[0]), "=r"(r[1]), "=r"(r[2]), "=r"(r[3]) : "r"(addr));
}
__device__ __forceinline__ void ldm_x4t(uint32_t* r, uint32_t addr) {
    asm volatile("ldmatrix.sync.aligned.m8n8.x4.trans.shared.b16 {%0,%1,%2,%3}, [%4];"
                 : "=r"(r[0]), "=r"(r[1]), "=r"(r[2]), "=r"(r[3]) : "r"(addr));
}
__device__ __forceinline__ void mma_f16(float* c, const uint32_t* a, const uint32_t* b) {
    asm volatile("mma.sync.aligned.m16n8k16.row.col.f32.f16.f16.f32 "
                 "{%0,%1,%2,%3}, {%4,%5,%6,%7}, {%8,%9}, {%0,%1,%2,%3};"
                 : "+f"(c[0]), "+f"(c[1]), "+f"(c[2]), "+f"(c[3])
                 : "r"(a[0]), "r"(a[1]), "r"(a[2]), "r"(a[3]), "r"(b[0]), "r"(b[1]));
}

// ---------------- fused weight transpose + fp32->fp16 (+scale) -------------
__global__ void transp_all(const float* __restrict__ wq, const float* __restrict__ wk,
                           const float* __restrict__ wv, const float* __restrict__ wo,
                           const float* __restrict__ w1, const float* __restrict__ w2,
                           __half* __restrict__ wqkvT, __half* __restrict__ woT,
                           __half* __restrict__ w1T, __half* __restrict__ w2T,
                           float qscale)
{
    int t = blockIdx.x;
    const float* W; __half* Wt; int K, N, tx, tloc; float scale = 1.0f;
    if (t < 1024) {
        K = 512; N = 512; tx = 16;
        tloc = t & 255;
        int seg = t >> 8;
        if (seg == 0)      { W = wq; Wt = wqkvT;               scale = qscale; }
        else if (seg == 1) { W = wk; Wt = wqkvT + 512 * 512; }
        else if (seg == 2) { W = wv; Wt = wqkvT + 1024 * 512; }
        else               { W = wo; Wt = woT; }
    } else if (t < 2048) {
        W = w1; Wt = w1T; K = 512; N = 2048; tx = 64; tloc = t - 1024;
    } else {
        W = w2; Wt = w2T; K = 2048; N = 512; tx = 16; tloc = t - 2048;
    }
    int n0 = (tloc % tx) * 32, k0 = (tloc / tx) * 32;

    __shared__ float tbuf[32][33];
    int x = threadIdx.x, y = threadIdx.y;   // 32 x 8
    #pragma unroll
    for (int i = 0; i < 32; i += 8)
        tbuf[y + i][x] = W[(size_t)(k0 + y + i) * N + n0 + x];
    __syncthreads();
    #pragma unroll
    for (int i = 0; i < 32; i += 8)
        Wt[(size_t)(n0 + y + i) * K + k0 + x] = __float2half(tbuf[x][y + i] * scale);
}

__global__ void bias_cat_kernel(const float* __restrict__ bq, const float* __restrict__ bk,
                                const float* __restrict__ bv, float* __restrict__ bqkv,
                                float qscale)
{
    int i = blockIdx.x * 256 + threadIdx.x;
    if (i < 512)       bqkv[i] = bq[i] * qscale;
    else if (i < 1024) bqkv[i] = bk[i - 512];
    else               bqkv[i] = bv[i - 1024];
}

// ----------------------- LayerNorm (+permute), fp16 out --------------------
__global__ void ln_kernel(const float* __restrict__ x,
                          const float* __restrict__ g,
                          const float* __restrict__ b,
                          __half* __restrict__ out, int permute)
{
    int t = blockIdx.x;
    int src = t;
    if (permute) {
        int bb  = t >> 12;
        int win = (t >> 6) & 63;
        int n   = t & 63;
        int hs  = ((win >> 3) << 3) + (n >> 3);
        int ws  = ((win & 7) << 3) + (n & 7);
        int h   = (hs + 4) & 63;
        int w   = (ws + 4) & 63;
        src = (bb << 12) + (h << 6) + w;
    }
    int tid = threadIdx.x;  // 128
    float4 val = ((const float4*)(x + (size_t)src * C_DIM))[tid];
    float s  = val.x + val.y + val.z + val.w;
    float s2 = val.x*val.x + val.y*val.y + val.z*val.z + val.w*val.w;
    #pragma unroll
    for (int o = 16; o; o >>= 1) {
        s  += __shfl_xor_sync(0xffffffffu, s,  o);
        s2 += __shfl_xor_sync(0xffffffffu, s2, o);
    }
    __shared__ float sb[4], s2b[4];
    int warp = tid >> 5, lane = tid & 31;
    if (lane == 0) { sb[warp] = s; s2b[warp] = s2; }
    __syncthreads();
    s  = sb[0] + sb[1] + sb[2] + sb[3];
    s2 = s2b[0] + s2b[1] + s2b[2] + s2b[3];
    float mean = s * (1.0f / C_DIM);
    float var  = s2 * (1.0f / C_DIM) - mean * mean;
    float inv  = rsqrtf(var + 1e-5f);
    float4 gg  = ((const float4*)g)[tid];
    float4 bb4 = ((const float4*)b)[tid];
    float o0 = (val.x - mean) * inv * gg.x + bb4.x;
    float o1 = (val.y - mean) * inv * gg.y + bb4.y;
    float o2 = (val.z - mean) * inv * gg.z + bb4.z;
    float o3 = (val.w - mean) * inv * gg.w + bb4.w;
    __half2 p0 = __floats2half2_rn(o0, o1);
    __half2 p1 = __floats2half2_rn(o2, o3);
    __half2* op = (__half2*)(out + (size_t)t * C_DIM) + 2 * tid;
    op[0] = p0; op[1] = p1;
}

// ------------------------- fp16 mma.sync GEMM ------------------------------
// C[M, Nt] = epi( A[M,K]fp16 @ Bt[Nt,K]fp16^T + bias )
// mode 0: fp16 out   mode 1: fp32 permuted row + res
// mode 2: fp16 GELU  mode 3: fp32 + res
// CTA tile 128x128, 256 threads (8 warps of 64x32), k-chunk 64, 3-stage
// cp.async, single __syncthreads per chunk, 2 CTAs/SM.

#define STAGES 3
#define ROWB   144                      // 128 data bytes + 16 pad
#define A_SZ   (128 * ROWB)             // 18432
#define STG_B  (2 * 128 * ROWB)         // 36864 per stage
#define SMEM_TOT (STAGES * STG_B)       // 110592 (x2 CTAs = 221184)

__global__ __launch_bounds__(256, 2)
void gemm_tc(const __half* __restrict__ A, const __half* __restrict__ Bt,
             const float* __restrict__ bias, const float* __restrict__ res,
             void* __restrict__ outp, int K, int Nt, int mode)
{
    extern __shared__ char smem[];
    const uint32_t su = smem_u32(smem);
    const int tid = threadIdx.x, wid = tid >> 5, lane = tid & 31;
    const int m0 = blockIdx.x * 128, n0 = blockIdx.y * 128;
    const int wm0 = (wid & 1) * 64, wn0 = (wid >> 1) * 32;

    // load slots: per thread 4 x 16B A + 4 x 16B B; slot j at row r0+32*j.
    // r = (tid>>3) + 32*j, c = tid&7  (8 chunks of 16B per 128-byte k-chunk row)
    int r0r = tid >> 3, cc0 = tid & 7;
    const char* aG0 = (const char*)(A  + (size_t)(m0 + r0r) * K + cc0 * 8);
    const char* bG0 = (const char*)(Bt + (size_t)(n0 + r0r) * K + cc0 * 8);
    const size_t aStride = (size_t)32 * K * 2;   // 32 rows
    uint32_t aS0 = su + r0r * ROWB + cc0 * 16;
    uint32_t bS0 = su + A_SZ + r0r * ROWB + cc0 * 16;

    const int NC = K >> 6;                // k-chunks of 64

    #pragma unroll
    for (int s = 0; s < STAGES - 1; s++) {
        int koff = s * 128;               // bytes (64 halves)
        #pragma unroll
        for (int j = 0; j < 4; j++) {
            cp_async16(aS0 + j * (32 * ROWB) + s * STG_B, aG0 + j * aStride + koff);
            cp_async16(bS0 + j * (32 * ROWB) + s * STG_B, bG0 + j * aStride + koff);
        }
        cp_commit();
    }

    float acc[4][4][4];
    #pragma unroll
    for (int mt = 0; mt < 4; mt++)
        #pragma unroll
        for (int nt = 0; nt < 4; nt++)
            #pragma unroll
            for (int i = 0; i < 4; i++) acc[mt][nt][i] = 0.0f;

    uint32_t aRow = (lane & 7) + ((lane >> 3) & 1) * 8;
    uint32_t aKof = (lane >> 4) * 16;
    uint32_t aBase = su + (wm0 + aRow) * ROWB + aKof;
    uint32_t bRow = (lane & 7) + ((lane >> 4)) * 8;
    uint32_t bKof = ((lane >> 3) & 1) * 16;
    uint32_t bBase = su + A_SZ + (wn0 + bRow) * ROWB + bKof;

    int cur = 0;
    for (int ch = 0; ch < NC; ch++) {
        int wst = cur + (STAGES - 1); if (wst >= STAGES) wst -= STAGES;
        cp_wait1();
        __syncthreads();

        // issue next chunk's loads first (overlap with compute below).
        // WAR safe: stage wst was last read in iteration ch-1, and all warps
        // have passed this iteration's barrier.
        int nx = ch + STAGES - 1;
        if (nx < NC) {
            int koff = nx * 128;
            #pragma unroll
            for (int j = 0; j < 4; j++) {
                cp_async16(aS0 + j * (32 * ROWB) + wst * STG_B, aG0 + j * aStride + koff);
                cp_async16(bS0 + j * (32 * ROWB) + wst * STG_B, bG0 + j * aStride + koff);
            }
        }
        cp_commit();

        uint32_t aStage = aBase + cur * STG_B;
        uint32_t bStage = bBase + cur * STG_B;
        #pragma unroll
        for (int k16 = 0; k16 < 4; k16++) {
            uint32_t bf[2][4];
            ldm_x4(bf[0], bStage + k16 * 32);
            ldm_x4(bf[1], bStage + 16 * ROWB + k16 * 32);
            #pragma unroll
            for (int mt = 0; mt < 4; mt++) {
                uint32_t af[4];
                ldm_x4(af, aStage + mt * 16 * ROWB + k16 * 32);
                #pragma unroll
                for (int nt = 0; nt < 4; nt++)
                    mma_f16(acc[mt][nt], af, &bf[nt >> 1][(nt & 1) * 2]);
            }
        }
        cur++; if (cur >= STAGES) cur = 0;
    }

    // epilogue
    int rl = lane >> 2, c2 = (lane & 3) * 2;
    #pragma unroll
    for (int mt = 0; mt < 4; mt++) {
        int rows[2] = { m0 + wm0 + mt * 16 + rl, m0 + wm0 + mt * 16 + rl + 8 };
        int orows[2] = { rows[0], rows[1] };
        if (mode == 1) {
            #pragma unroll
            for (int h = 0; h < 2; h++) {
                int row = rows[h];
                int bb  = row >> 12;
                int win = (row >> 6) & 63;
                int n   = row & 63;
                int hs  = ((win >> 3) << 3) + (n >> 3);
                int ws  = ((win & 7) << 3) + (n & 7);
                int hh  = (hs + 4) & 63;
                int ww  = (ws + 4) & 63;
                orows[h] = (bb << 12) + (hh << 6) + ww;
            }
        }
        #pragma unroll
        for (int nt = 0; nt < 4; nt++) {
            int col = n0 + wn0 + nt * 8 + c2;
            float bia0 = bias[col], bia1 = bias[col + 1];
            #pragma unroll
            for (int h = 0; h < 2; h++) {
                float v0 = acc[mt][nt][h * 2]     + bia0;
                float v1 = acc[mt][nt][h * 2 + 1] + bia1;
                size_t rb = (size_t)orows[h] * Nt + col;
                if (mode == 0) {
                    *(__half2*)((__half*)outp + rb) = __floats2half2_rn(v0, v1);
                } else if (mode == 2) {
                    v0 = 0.5f * v0 * (1.0f + erff(v0 * 0.70710678118654752f));
                    v1 = 0.5f * v1 * (1.0f + erff(v1 * 0.70710678118654752f));
                    *(__half2*)((__half*)outp + rb) = __floats2half2_rn(v0, v1);
                } else {
                    float2 r2 = *(const float2*)(res + rb);
                    float2 o2; o2.x = v0 + r2.x; o2.y = v1 + r2.y;
                    *(float2*)((float*)outp + rb) = o2;
                }
            }
        }
    }
}

// ------------------- tensor-core windowed attention ------------------------
#define APITCH 80   // bytes per 32-dim row (64 data + 16 pad)

__global__ __launch_bounds__(256)
void attn_tc(const __half* __restrict__ qkv,
             const float* __restrict__ bias_table,
             __half* __restrict__ ctx)
{
    int blk = blockIdx.x;           // 512 * 8
    int w  = blk >> 3;
    int hp = blk & 7;
    int tid = threadIdx.x, wid = tid >> 5, lane = tid & 31;
    int hd  = wid >> 2;
    int hh  = hp * 2 + hd;
    int r0  = (wid & 3) * 16;

    __shared__ __half sm[2 * 3 * 64 * (APITCH / 2)];

    #pragma unroll
    for (int j = 0; j < 6; j++) {
        int idx = tid + j * 256;
        int head = idx / 768;
        int rem  = idx - head * 768;
        int te   = rem >> 8;
        int r2   = rem & 255;
        int row  = r2 >> 2;
        int chk  = r2 & 3;
        const uint4* src = (const uint4*)(qkv + (size_t)(w * 64 + row) * QKVD
                                          + te * 512 + (hp * 2 + head) * 32 + chk * 8);
        uint4* dst = (uint4*)(sm + ((head * 3 + te) * 64 + row) * 40 + chk * 8);
        *dst = *src;
    }
    __syncthreads();

    uint32_t smb = smem_u32(sm);
    uint32_t qB = smb + (hd * 3 + 0) * 64 * APITCH;
    uint32_t kB = smb + (hd * 3 + 1) * 64 * APITCH;
    uint32_t vB = smb + (hd * 3 + 2) * 64 * APITCH;

    float sacc[8][4];
    #pragma unroll
    for (int nt = 0; nt < 8; nt++)
        #pragma unroll
        for (int i = 0; i < 4; i++) sacc[nt][i] = 0.0f;

    uint32_t aRow = r0 + (lane & 7) + ((lane >> 3) & 1) * 8;
    uint32_t aKof = (lane >> 4) * 16;
    uint32_t bRowB = (lane & 7) + (lane >> 4) * 8;
    uint32_t bKof = ((lane >> 3) & 1) * 16;

    #pragma unroll
    for (int k16 = 0; k16 < 2; k16++) {
        uint32_t af[4];
        ldm_x4(af, qB + aRow * APITCH + aKof + k16 * 32);
        #pragma unroll
        for (int g = 0; g < 4; g++) {
            uint32_t bf[4];
            ldm_x4(bf, kB + (g * 16 + bRowB) * APITCH + bKof + k16 * 32);
            mma_f16(sacc[2 * g],     af, &bf[0]);
            mma_f16(sacc[2 * g + 1], af, &bf[2]);
        }
    }

    int win = w & 63;
    int wh = win >> 3, ww = win & 7;
    int ra = r0 + (lane >> 2);
    int cbase = (lane & 3) * 2;
    #pragma unroll
    for (int hrow = 0; hrow < 2; hrow++) {
        int r = ra + hrow * 8;
        int i1 = r >> 3, j1 = r & 7;
        int hs1 = wh * 8 + i1, ws1 = ww * 8 + j1;
        int reg1 = (hs1 < 56 ? 0 : (hs1 < 60 ? 1 : 2)) * 3 + (ws1 < 56 ? 0 : (ws1 < 60 ? 1 : 2));
        #pragma unroll
        for (int nt = 0; nt < 8; nt++) {
            #pragma unroll
            for (int cc = 0; cc < 2; cc++) {
                int col = nt * 8 + cbase + cc;
                int j2 = col & 7;
                int rel = (i1 - nt + 7) * 15 + (j1 - j2 + 7);
                float s = sacc[nt][hrow * 2 + cc] + bias_table[rel * HEADS_N + hh];
                int hs2 = wh * 8 + nt, ws2 = ww * 8 + j2;
                int reg2 = (hs2 < 56 ? 0 : (hs2 < 60 ? 1 : 2)) * 3 + (ws2 < 56 ? 0 : (ws2 < 60 ? 1 : 2));
                if (reg1 != reg2) s -= 100.0f;
                sacc[nt][hrow * 2 + cc] = s;
            }
        }
    }

    #pragma unroll
    for (int hrow = 0; hrow < 2; hrow++) {
        float mx = -1e30f;
        #pragma unroll
        for (int nt = 0; nt < 8; nt++)
            mx = fmaxf(mx, fmaxf(sacc[nt][hrow * 2], sacc[nt][hrow * 2 + 1]));
        mx = fmaxf(mx, __shfl_xor_sync(0xffffffffu, mx, 1));
        mx = fmaxf(mx, __shfl_xor_sync(0xffffffffu, mx, 2));
        float sum = 0.0f;
        #pragma unroll
        for (int nt = 0; nt < 8; nt++) {
            float e0 = expf(sacc[nt][hrow * 2]     - mx);
            float e1 = expf(sacc[nt][hrow * 2 + 1] - mx);
            sacc[nt][hrow * 2] = e0; sacc[nt][hrow * 2 + 1] = e1;
            sum += e0 + e1;
        }
        sum += __shfl_xor_sync(0xffffffffu, sum, 1);
        sum += __shfl_xor_sync(0xffffffffu, sum, 2);
        float inv = 1.0f / sum;
        #pragma unroll
        for (int nt = 0; nt < 8; nt++) {
            sacc[nt][hrow * 2]     *= inv;
            sacc[nt][hrow * 2 + 1] *= inv;
        }
    }

    uint32_t pa[4][4];
    #pragma unroll
    for (int ks = 0; ks < 4; ks++) {
        __half2 t0 = __floats2half2_rn(sacc[2 * ks][0],     sacc[2 * ks][1]);
        __half2 t1 = __floats2half2_rn(sacc[2 * ks][2],     sacc[2 * ks][3]);
        __half2 t2 = __floats2half2_rn(sacc[2 * ks + 1][0], sacc[2 * ks + 1][1]);
        __half2 t3 = __floats2half2_rn(sacc[2 * ks + 1][2], sacc[2 * ks + 1][3]);
        pa[ks][0] = *(uint32_t*)&t0; pa[ks][1] = *(uint32_t*)&t1;
        pa[ks][2] = *(uint32_t*)&t2; pa[ks][3] = *(uint32_t*)&t3;
    }

    float oacc[4][4];
    #pragma unroll
    for (int nt = 0; nt < 4; nt++)
        #pragma unroll
        for (int i = 0; i < 4; i++) oacc[nt][i] = 0.0f;

    uint32_t vRow = (lane & 7) + ((lane >> 3) & 1) * 8;
    uint32_t vOff = (lane >> 4) * 16;
    #pragma unroll
    for (int ks = 0; ks < 4; ks++) {
        uint32_t vf0[4], vf1[4];
        uint32_t base = vB + (ks * 16 + vRow) * APITCH;
        ldm_x4t(vf0, base + vOff);
        ldm_x4t(vf1, base + 32 + vOff);
        mma_f16(oacc[0], pa[ks], &vf0[0]);
        mma_f16(oacc[1], pa[ks], &vf0[2]);
        mma_f16(oacc[2], pa[ks], &vf1[0]);
        mma_f16(oacc[3], pa[ks], &vf1[2]);
    }

    #pragma unroll
    for (int hrow = 0; hrow < 2; hrow++) {
        int row = w * 64 + ra + hrow * 8;
        #pragma unroll
        for (int nt = 0; nt < 4; nt++) {
            int col = hh * 32 + nt * 8 + cbase;
            __half2 p = __floats2half2_rn(oacc[nt][hrow * 2], oacc[nt][hrow * 2 + 1]);
            *(__half2*)(ctx + (size_t)row * C_DIM + col) = p;
        }
    }
}

// ------------------------------- launcher ----------------------------------
extern "C" void kernel_launch(void* const* d_in, const int* in_sizes, int n_in,
                              void* d_out, int out_size)
{
    const float* x      = (const float*)d_in[0];
    const float* ln1_g  = (const float*)d_in[1];
    const float* ln1_b  = (const float*)d_in[2];
    const float* wq     = (const float*)d_in[3];
    const float* bq     = (const float*)d_in[4];
    const float* wk     = (const float*)d_in[5];
    const float* bk     = (const float*)d_in[6];
    const float* wv     = (const float*)d_in[7];
    const float* bv     = (const float*)d_in[8];
    const float* relt   = (const float*)d_in[9];
    const float* wo     = (const float*)d_in[10];
    const float* bo     = (const float*)d_in[11];
    const float* ln2_g  = (const float*)d_in[12];
    const float* ln2_b  = (const float*)d_in[13];
    const float* w1     = (const float*)d_in[14];
    const float* b1     = (const float*)d_in[15];
    const float* w2     = (const float*)d_in[16];
    const float* b2     = (const float*)d_in[17];
    float* out          = (float*)d_out;

    float *p_hid, *p_bqkv;
    __half *p_xw, *p_qkv, *p_ctx, *p_y, *p_h1;
    __half *p_wqkvT, *p_woT, *p_w1T, *p_w2T;
    cudaGetSymbolAddress((void**)&p_hid,   g_hid);
    cudaGetSymbolAddress((void**)&p_bqkv,  g_bqkv);
    cudaGetSymbolAddress((void**)&p_xw,    h_xw);
    cudaGetSymbolAddress((void**)&p_qkv,   h_qkv);
    cudaGetSymbolAddress((void**)&p_ctx,   h_ctx);
    cudaGetSymbolAddress((void**)&p_y,     h_y);
    cudaGetSymbolAddress((void**)&p_h1,    h_h1);
    cudaGetSymbolAddress((void**)&p_wqkvT, h_wqkvT);
    cudaGetSymbolAddress((void**)&p_woT,   h_woT);
    cudaGetSymbolAddress((void**)&p_w1T,   h_w1T);
    cudaGetSymbolAddress((void**)&p_w2T,   h_w2T);

    cudaFuncSetAttribute(gemm_tc, cudaFuncAttributeMaxDynamicSharedMemorySize, SMEM_TOT);

    const float qscale = 0.17677669529663689f;  // 1/sqrt(32)

    // 0. all weight transposes in one launch + bias concat
    dim3 tb(32, 8);
    transp_all<<<3072, tb>>>(wq, wk, wv, wo, w1, w2,
                             p_wqkvT, p_woT, p_w1T, p_w2T, qscale);
    bias_cat_kernel<<<6, 256>>>(bq, bk, bv, p_bqkv, qscale);

    // 1. LN1 + shift + window partition (fp16)
    ln_kernel<<<T_TOK, 128>>>(x, ln1_g, ln1_b, p_xw, 1);

    // 2. fused QKV projection (fp16 out)
    dim3 gqkv(T_TOK / 128, QKVD / 128);
    gemm_tc<<<gqkv, 256, SMEM_TOT>>>(p_xw, p_wqkvT, p_bqkv, nullptr, p_qkv, C_DIM, QKVD, 0);

    // 3. tensor-core windowed attention
    attn_tc<<<512 * 8, 256>>>(p_qkv, relt, p_ctx);

    // 4. output proj + window reverse + residual (fp32)
    dim3 g4(T_TOK / 128, C_DIM / 128);
    gemm_tc<<<g4, 256, SMEM_TOT>>>(p_ctx, p_woT, bo, x, p_hid, C_DIM, C_DIM, 1);

    // 5. LN2 (fp16 out)
    ln_kernel<<<T_TOK, 128>>>(p_hid, ln2_g, ln2_b, p_y, 0);

    // 6. MLP fc1 + GELU (fp16 out)
    dim3 g16(T_TOK / 128, MLPD / 128);
    gemm_tc<<<g16, 256, SMEM_TOT>>>(p_y, p_w1T, b1, nullptr, p_h1, C_DIM, MLPD, 2);

    // 7. MLP fc2 + residual -> out (fp32)
    gemm_tc<<<g4, 256, SMEM_TOT>>>(p_h1, p_w2T, b2, p_hid, out, MLPD, C_DIM, 3);
}

// round 14
// speedup vs baseline: 1.4211x; 1.4211x over previous
#include <cuda_runtime.h>
#include <cuda_fp16.h>
#include <cstdint>

// ---------------------------------------------------------------------------
// Swin block on GB300 (sm_103 plain target): fp16 mma.sync GEMMs (128x128 CTA
// tile, 8 warps of 64x32, k-chunk 32, 5-stage cp.async, single-barrier
// mainloop, 2 CTAs/SM); tensor-core windowed attention; fp32 LN/residual.
// ---------------------------------------------------------------------------

#define T_TOK   32768
#define C_DIM   512
#define QKVD    1536
#define MLPD    2048
#define HEADS_N 16

// ------------------------------- scratch -----------------------------------
__device__ float g_hid[(size_t)T_TOK * C_DIM];
__device__ float g_bqkv[QKVD];
__device__ __half h_xw  [(size_t)T_TOK * C_DIM];
__device__ __half h_qkv [(size_t)T_TOK * QKVD];
__device__ __half h_ctx [(size_t)T_TOK * C_DIM];
__device__ __half h_y   [(size_t)T_TOK * C_DIM];
__device__ __half h_h1  [(size_t)T_TOK * MLPD];
__device__ __half h_wqkvT[(size_t)QKVD * C_DIM];
__device__ __half h_woT [(size_t)C_DIM * C_DIM];
__device__ __half h_w1T [(size_t)MLPD * C_DIM];
__device__ __half h_w2T [(size_t)C_DIM * MLPD];

// ------------------------------- helpers -----------------------------------
__device__ __forceinline__ uint32_t smem_u32(const void* p) {
    uint32_t a;
    asm("{ .reg .u64 t; cvta.to.shared.u64 t, %1; cvt.u32.u64 %0, t; }"
        : "=r"(a) : "l"(p));
    return a;
}
__device__ __forceinline__ void cp_async16(uint32_t dst, const void* src) {
    asm volatile("cp.async.cg.shared.global [%0], [%1], 16;" :: "r"(dst), "l"(src));
}
__device__ __forceinline__ void cp_commit() { asm volatile("cp.async.commit_group;"); }
__device__ __forceinline__ void cp_wait3()  { asm volatile("cp.async.wait_group 3;" ::: "memory"); }

__device__ __forceinline__ void ldm_x4(uint32_t* r, uint32_t addr) {
    asm volatile("ldmatrix.sync.aligned.m8n8.x4.shared.b16 {%0,%1,%2,%3}, [%4];"
                 : "=r"(r[0]), "=r"(r[1]), "=r"(r[2]), "=r"(r[3]) : "r"(addr));
}
__device__ __forceinline__ void ldm_x4t(uint32_t* r, uint32_t addr) {
    asm volatile("ldmatrix.sync.aligned.m8n8.x4.trans.shared.b16 {%0,%1,%2,%3}, [%4];"
                 : "=r"(r[0]), "=r"(r[1]), "=r"(r[2]), "=r"(r[3]) : "r"(addr));
}
__device__ __forceinline__ void mma_f16(float* c, const uint32_t* a, const uint32_t* b) {
    asm volatile("mma.sync.aligned.m16n8k16.row.col.f32.f16.f16.f32 "
                 "{%0,%1,%2,%3}, {%4,%5,%6,%7}, {%8,%9}, {%0,%1,%2,%3};"
                 : "+f"(c[0]), "+f"(c[1]), "+f"(c[2]), "+f"(c[3])
                 : "r"(a[0]), "r"(a[1]), "r"(a[2]), "r"(a[3]), "r"(b[0]), "r"(b[1]));
}

// ---------------- fused weight transpose + fp32->fp16 (+scale) -------------
__global__ void transp_all(const float* __restrict__ wq, const float* __restrict__ wk,
                           const float* __restrict__ wv, const float* __restrict__ wo,
                           const float* __restrict__ w1, const float* __restrict__ w2,
                           __half* __restrict__ wqkvT, __half* __restrict__ woT,
                           __half* __restrict__ w1T, __half* __restrict__ w2T,
                           float qscale)
{
    int t = blockIdx.x;
    const float* W; __half* Wt; int K, N, tx, tloc; float scale = 1.0f;
    if (t < 1024) {
        K = 512; N = 512; tx = 16;
        tloc = t & 255;
        int seg = t >> 8;
        if (seg == 0)      { W = wq; Wt = wqkvT;               scale = qscale; }
        else if (seg == 1) { W = wk; Wt = wqkvT + 512 * 512; }
        else if (seg == 2) { W = wv; Wt = wqkvT + 1024 * 512; }
        else               { W = wo; Wt = woT; }
    } else if (t < 2048) {
        W = w1; Wt = w1T; K = 512; N = 2048; tx = 64; tloc = t - 1024;
    } else {
        W = w2; Wt = w2T; K = 2048; N = 512; tx = 16; tloc = t - 2048;
    }
    int n0 = (tloc % tx) * 32, k0 = (tloc / tx) * 32;

    __shared__ float tbuf[32][33];
    int x = threadIdx.x, y = threadIdx.y;   // 32 x 8
    #pragma unroll
    for (int i = 0; i < 32; i += 8)
        tbuf[y + i][x] = W[(size_t)(k0 + y + i) * N + n0 + x];
    __syncthreads();
    #pragma unroll
    for (int i = 0; i < 32; i += 8)
        Wt[(size_t)(n0 + y + i) * K + k0 + x] = __float2half(tbuf[x][y + i] * scale);
}

__global__ void bias_cat_kernel(const float* __restrict__ bq, const float* __restrict__ bk,
                                const float* __restrict__ bv, float* __restrict__ bqkv,
                                float qscale)
{
    int i = blockIdx.x * 256 + threadIdx.x;
    if (i < 512)       bqkv[i] = bq[i] * qscale;
    else if (i < 1024) bqkv[i] = bk[i - 512];
    else               bqkv[i] = bv[i - 1024];
}

// ----------------------- LayerNorm (+permute), fp16 out --------------------
__global__ void ln_kernel(const float* __restrict__ x,
                          const float* __restrict__ g,
                          const float* __restrict__ b,
                          __half* __restrict__ out, int permute)
{
    int t = blockIdx.x;
    int src = t;
    if (permute) {
        int bb  = t >> 12;
        int win = (t >> 6) & 63;
        int n   = t & 63;
        int hs  = ((win >> 3) << 3) + (n >> 3);
        int ws  = ((win & 7) << 3) + (n & 7);
        int h   = (hs + 4) & 63;
        int w   = (ws + 4) & 63;
        src = (bb << 12) + (h << 6) + w;
    }
    int tid = threadIdx.x;  // 128
    float4 val = ((const float4*)(x + (size_t)src * C_DIM))[tid];
    float s  = val.x + val.y + val.z + val.w;
    float s2 = val.x*val.x + val.y*val.y + val.z*val.z + val.w*val.w;
    #pragma unroll
    for (int o = 16; o; o >>= 1) {
        s  += __shfl_xor_sync(0xffffffffu, s,  o);
        s2 += __shfl_xor_sync(0xffffffffu, s2, o);
    }
    __shared__ float sb[4], s2b[4];
    int warp = tid >> 5, lane = tid & 31;
    if (lane == 0) { sb[warp] = s; s2b[warp] = s2; }
    __syncthreads();
    s  = sb[0] + sb[1] + sb[2] + sb[3];
    s2 = s2b[0] + s2b[1] + s2b[2] + s2b[3];
    float mean = s * (1.0f / C_DIM);
    float var  = s2 * (1.0f / C_DIM) - mean * mean;
    float inv  = rsqrtf(var + 1e-5f);
    float4 gg  = ((const float4*)g)[tid];
    float4 bb4 = ((const float4*)b)[tid];
    float o0 = (val.x - mean) * inv * gg.x + bb4.x;
    float o1 = (val.y - mean) * inv * gg.y + bb4.y;
    float o2 = (val.z - mean) * inv * gg.z + bb4.z;
    float o3 = (val.w - mean) * inv * gg.w + bb4.w;
    __half2 p0 = __floats2half2_rn(o0, o1);
    __half2 p1 = __floats2half2_rn(o2, o3);
    __half2* op = (__half2*)(out + (size_t)t * C_DIM) + 2 * tid;
    op[0] = p0; op[1] = p1;
}

// ------------------------- fp16 mma.sync GEMM ------------------------------
// C[M, Nt] = epi( A[M,K]fp16 @ Bt[Nt,K]fp16^T + bias )
// mode 0: fp16 out   mode 1: fp32 permuted row + res
// mode 2: fp16 GELU  mode 3: fp32 + res
// CTA tile 128x128, 256 threads (8 warps of 64x32), k-chunk 32, 5-stage
// cp.async, single __syncthreads per chunk, 2 CTAs/SM.

#define STAGES 5
#define ROWB   80
#define A_SZ   (128 * ROWB)             // 10240
#define STG_B  (2 * 128 * ROWB)         // 20480 per stage
#define SMEM_TOT (STAGES * STG_B)       // 102400 (x2 CTAs = 204800)

__global__ __launch_bounds__(256, 2)
void gemm_tc(const __half* __restrict__ A, const __half* __restrict__ Bt,
             const float* __restrict__ bias, const float* __restrict__ res,
             void* __restrict__ outp, int K, int Nt, int mode)
{
    extern __shared__ char smem[];
    const uint32_t su = smem_u32(smem);
    const int tid = threadIdx.x, wid = tid >> 5, lane = tid & 31;
    const int m0 = blockIdx.x * 128, n0 = blockIdx.y * 128;
    const int wm0 = (wid & 1) * 64, wn0 = (wid >> 1) * 32;

    // load slots: 2x16B A, 2x16B B per thread (row = idx>>2, chunk = idx&3)
    const char* aG[2]; const char* bG[2];
    uint32_t aS[2], bS[2];
    #pragma unroll
    for (int j = 0; j < 2; j++) {
        int idx = tid + j * 256;
        int r = idx >> 2, c = idx & 3;
        aG[j] = (const char*)(A  + (size_t)(m0 + r) * K + c * 8);
        bG[j] = (const char*)(Bt + (size_t)(n0 + r) * K + c * 8);
        aS[j] = su + r * ROWB + c * 16;
        bS[j] = su + A_SZ + r * ROWB + c * 16;
    }

    const int NC = K >> 5;

    #pragma unroll
    for (int s = 0; s < STAGES - 1; s++) {
        int koff = s * 64;
        if (s < NC) {
            #pragma unroll
            for (int j = 0; j < 2; j++) {
                cp_async16(aS[j] + s * STG_B, aG[j] + koff);
                cp_async16(bS[j] + s * STG_B, bG[j] + koff);
            }
        }
        cp_commit();
    }

    float acc[4][4][4];
    #pragma unroll
    for (int mt = 0; mt < 4; mt++)
        #pragma unroll
        for (int nt = 0; nt < 4; nt++)
            #pragma unroll
            for (int i = 0; i < 4; i++) acc[mt][nt][i] = 0.0f;

    uint32_t aRow = (lane & 7) + ((lane >> 3) & 1) * 8;
    uint32_t aKof = (lane >> 4) * 16;
    uint32_t aBase = su + (wm0 + aRow) * ROWB + aKof;
    uint32_t bRow = (lane & 7) + ((lane >> 4)) * 8;
    uint32_t bKof = ((lane >> 3) & 1) * 16;
    uint32_t bBase = su + A_SZ + (wn0 + bRow) * ROWB + bKof;

    int cur = 0;
    for (int ch = 0; ch < NC; ch++) {
        int wst = cur + (STAGES - 1); if (wst >= STAGES) wst -= STAGES;
        cp_wait3();
        __syncthreads();

        // issue next chunk's loads first (overlap with compute below).
        // WAR safe: stage wst was last read in iteration ch-1, and all warps
        // have passed this iteration's barrier.
        int nx = ch + STAGES - 1;
        if (nx < NC) {
            int koff = nx * 64;
            #pragma unroll
            for (int j = 0; j < 2; j++) {
                cp_async16(aS[j] + wst * STG_B, aG[j] + koff);
                cp_async16(bS[j] + wst * STG_B, bG[j] + koff);
            }
        }
        cp_commit();

        uint32_t aStage = aBase + cur * STG_B;
        uint32_t bStage = bBase + cur * STG_B;
        #pragma unroll
        for (int k16 = 0; k16 < 2; k16++) {
            uint32_t bf[2][4];
            ldm_x4(bf[0], bStage + k16 * 32);
            ldm_x4(bf[1], bStage + 16 * ROWB + k16 * 32);
            #pragma unroll
            for (int mt = 0; mt < 4; mt++) {
                uint32_t af[4];
                ldm_x4(af, aStage + mt * 16 * ROWB + k16 * 32);
                #pragma unroll
                for (int nt = 0; nt < 4; nt++)
                    mma_f16(acc[mt][nt], af, &bf[nt >> 1][(nt & 1) * 2]);
            }
        }
        cur++; if (cur >= STAGES) cur = 0;
    }

    // epilogue
    int rl = lane >> 2, c2 = (lane & 3) * 2;
    #pragma unroll
    for (int mt = 0; mt < 4; mt++) {
        int rows[2] = { m0 + wm0 + mt * 16 + rl, m0 + wm0 + mt * 16 + rl + 8 };
        int orows[2] = { rows[0], rows[1] };
        if (mode == 1) {
            #pragma unroll
            for (int h = 0; h < 2; h++) {
                int row = rows[h];
                int bb  = row >> 12;
                int win = (row >> 6) & 63;
                int n   = row & 63;
                int hs  = ((win >> 3) << 3) + (n >> 3);
                int ws  = ((win & 7) << 3) + (n & 7);
                int hh  = (hs + 4) & 63;
                int ww  = (ws + 4) & 63;
                orows[h] = (bb << 12) + (hh << 6) + ww;
            }
        }
        #pragma unroll
        for (int nt = 0; nt < 4; nt++) {
            int col = n0 + wn0 + nt * 8 + c2;
            float bia0 = bias[col], bia1 = bias[col + 1];
            #pragma unroll
            for (int h = 0; h < 2; h++) {
                float v0 = acc[mt][nt][h * 2]     + bia0;
                float v1 = acc[mt][nt][h * 2 + 1] + bia1;
                size_t rb = (size_t)orows[h] * Nt + col;
                if (mode == 0) {
                    *(__half2*)((__half*)outp + rb) = __floats2half2_rn(v0, v1);
                } else if (mode == 2) {
                    v0 = 0.5f * v0 * (1.0f + erff(v0 * 0.70710678118654752f));
                    v1 = 0.5f * v1 * (1.0f + erff(v1 * 0.70710678118654752f));
                    *(__half2*)((__half*)outp + rb) = __floats2half2_rn(v0, v1);
                } else {
                    float2 r2 = *(const float2*)(res + rb);
                    float2 o2; o2.x = v0 + r2.x; o2.y = v1 + r2.y;
                    *(float2*)((float*)outp + rb) = o2;
                }
            }
        }
    }
}

// ------------------- tensor-core windowed attention ------------------------
#define APITCH 80   // bytes per 32-dim row (64 data + 16 pad)

__global__ __launch_bounds__(256)
void attn_tc(const __half* __restrict__ qkv,
             const float* __restrict__ bias_table,
             __half* __restrict__ ctx)
{
    int blk = blockIdx.x;           // 512 * 8
    int w  = blk >> 3;
    int hp = blk & 7;
    int tid = threadIdx.x, wid = tid >> 5, lane = tid & 31;
    int hd  = wid >> 2;
    int hh  = hp * 2 + hd;
    int r0  = (wid & 3) * 16;

    __shared__ __half sm[2 * 3 * 64 * (APITCH / 2)];

    #pragma unroll
    for (int j = 0; j < 6; j++) {
        int idx = tid + j * 256;
        int head = idx / 768;
        int rem  = idx - head * 768;
        int te   = rem >> 8;
        int r2   = rem & 255;
        int row  = r2 >> 2;
        int chk  = r2 & 3;
        const uint4* src = (const uint4*)(qkv + (size_t)(w * 64 + row) * QKVD
                                          + te * 512 + (hp * 2 + head) * 32 + chk * 8);
        uint4* dst = (uint4*)(sm + ((head * 3 + te) * 64 + row) * 40 + chk * 8);
        *dst = *src;
    }
    __syncthreads();

    uint32_t smb = smem_u32(sm);
    uint32_t qB = smb + (hd * 3 + 0) * 64 * APITCH;
    uint32_t kB = smb + (hd * 3 + 1) * 64 * APITCH;
    uint32_t vB = smb + (hd * 3 + 2) * 64 * APITCH;

    float sacc[8][4];
    #pragma unroll
    for (int nt = 0; nt < 8; nt++)
        #pragma unroll
        for (int i = 0; i < 4; i++) sacc[nt][i] = 0.0f;

    uint32_t aRow = r0 + (lane & 7) + ((lane >> 3) & 1) * 8;
    uint32_t aKof = (lane >> 4) * 16;
    uint32_t bRowB = (lane & 7) + (lane >> 4) * 8;
    uint32_t bKof = ((lane >> 3) & 1) * 16;

    #pragma unroll
    for (int k16 = 0; k16 < 2; k16++) {
        uint32_t af[4];
        ldm_x4(af, qB + aRow * APITCH + aKof + k16 * 32);
        #pragma unroll
        for (int g = 0; g < 4; g++) {
            uint32_t bf[4];
            ldm_x4(bf, kB + (g * 16 + bRowB) * APITCH + bKof + k16 * 32);
            mma_f16(sacc[2 * g],     af, &bf[0]);
            mma_f16(sacc[2 * g + 1], af, &bf[2]);
        }
    }

    int win = w & 63;
    int wh = win >> 3, ww = win & 7;
    int ra = r0 + (lane >> 2);
    int cbase = (lane & 3) * 2;
    #pragma unroll
    for (int hrow = 0; hrow < 2; hrow++) {
        int r = ra + hrow * 8;
        int i1 = r >> 3, j1 = r & 7;
        int hs1 = wh * 8 + i1, ws1 = ww * 8 + j1;
        int reg1 = (hs1 < 56 ? 0 : (hs1 < 60 ? 1 : 2)) * 3 + (ws1 < 56 ? 0 : (ws1 < 60 ? 1 : 2));
        #pragma unroll
        for (int nt = 0; nt < 8; nt++) {
            #pragma unroll
            for (int cc = 0; cc < 2; cc++) {
                int col = nt * 8 + cbase + cc;
                int j2 = col & 7;
                int rel = (i1 - nt + 7) * 15 + (j1 - j2 + 7);
                float s = sacc[nt][hrow * 2 + cc] + bias_table[rel * HEADS_N + hh];
                int hs2 = wh * 8 + nt, ws2 = ww * 8 + j2;
                int reg2 = (hs2 < 56 ? 0 : (hs2 < 60 ? 1 : 2)) * 3 + (ws2 < 56 ? 0 : (ws2 < 60 ? 1 : 2));
                if (reg1 != reg2) s -= 100.0f;
                sacc[nt][hrow * 2 + cc] = s;
            }
        }
    }

    #pragma unroll
    for (int hrow = 0; hrow < 2; hrow++) {
        float mx = -1e30f;
        #pragma unroll
        for (int nt = 0; nt < 8; nt++)
            mx = fmaxf(mx, fmaxf(sacc[nt][hrow * 2], sacc[nt][hrow * 2 + 1]));
        mx = fmaxf(mx, __shfl_xor_sync(0xffffffffu, mx, 1));
        mx = fmaxf(mx, __shfl_xor_sync(0xffffffffu, mx, 2));
        float sum = 0.0f;
        #pragma unroll
        for (int nt = 0; nt < 8; nt++) {
            float e0 = expf(sacc[nt][hrow * 2]     - mx);
            float e1 = expf(sacc[nt][hrow * 2 + 1] - mx);
            sacc[nt][hrow * 2] = e0; sacc[nt][hrow * 2 + 1] = e1;
            sum += e0 + e1;
        }
        sum += __shfl_xor_sync(0xffffffffu, sum, 1);
        sum += __shfl_xor_sync(0xffffffffu, sum, 2);
        float inv = 1.0f / sum;
        #pragma unroll
        for (int nt = 0; nt < 8; nt++) {
            sacc[nt][hrow * 2]     *= inv;
            sacc[nt][hrow * 2 + 1] *= inv;
        }
    }

    uint32_t pa[4][4];
    #pragma unroll
    for (int ks = 0; ks < 4; ks++) {
        __half2 t0 = __floats2half2_rn(sacc[2 * ks][0],     sacc[2 * ks][1]);
        __half2 t1 = __floats2half2_rn(sacc[2 * ks][2],     sacc[2 * ks][3]);
        __half2 t2 = __floats2half2_rn(sacc[2 * ks + 1][0], sacc[2 * ks + 1][1]);
        __half2 t3 = __floats2half2_rn(sacc[2 * ks + 1][2], sacc[2 * ks + 1][3]);
        pa[ks][0] = *(uint32_t*)&t0; pa[ks][1] = *(uint32_t*)&t1;
        pa[ks][2] = *(uint32_t*)&t2; pa[ks][3] = *(uint32_t*)&t3;
    }

    float oacc[4][4];
    #pragma unroll
    for (int nt = 0; nt < 4; nt++)
        #pragma unroll
        for (int i = 0; i < 4; i++) oacc[nt][i] = 0.0f;

    uint32_t vRow = (lane & 7) + ((lane >> 3) & 1) * 8;
    uint32_t vOff = (lane >> 4) * 16;
    #pragma unroll
    for (int ks = 0; ks < 4; ks++) {
        uint32_t vf0[4], vf1[4];
        uint32_t base = vB + (ks * 16 + vRow) * APITCH;
        ldm_x4t(vf0, base + vOff);
        ldm_x4t(vf1, base + 32 + vOff);
        mma_f16(oacc[0], pa[ks], &vf0[0]);
        mma_f16(oacc[1], pa[ks], &vf0[2]);
        mma_f16(oacc[2], pa[ks], &vf1[0]);
        mma_f16(oacc[3], pa[ks], &vf1[2]);
    }

    #pragma unroll
    for (int hrow = 0; hrow < 2; hrow++) {
        int row = w * 64 + ra + hrow * 8;
        #pragma unroll
        for (int nt = 0; nt < 4; nt++) {
            int col = hh * 32 + nt * 8 + cbase;
            __half2 p = __floats2half2_rn(oacc[nt][hrow * 2], oacc[nt][hrow * 2 + 1]);
            *(__half2*)(ctx + (size_t)row * C_DIM + col) = p;
        }
    }
}

// ------------------------------- launcher ----------------------------------
extern "C" void kernel_launch(void* const* d_in, const int* in_sizes, int n_in,
                              void* d_out, int out_size)
{
    const float* x      = (const float*)d_in[0];
    const float* ln1_g  = (const float*)d_in[1];
    const float* ln1_b  = (const float*)d_in[2];
    const float* wq     = (const float*)d_in[3];
    const float* bq     = (const float*)d_in[4];
    const float* wk     = (const float*)d_in[5];
    const float* bk     = (const float*)d_in[6];
    const float* wv     = (const float*)d_in[7];
    const float* bv     = (const float*)d_in[8];
    const float* relt   = (const float*)d_in[9];
    const float* wo     = (const float*)d_in[10];
    const float* bo     = (const float*)d_in[11];
    const float* ln2_g  = (const float*)d_in[12];
    const float* ln2_b  = (const float*)d_in[13];
    const float* w1     = (const float*)d_in[14];
    const float* b1     = (const float*)d_in[15];
    const float* w2     = (const float*)d_in[16];
    const float* b2     = (const float*)d_in[17];
    float* out          = (float*)d_out;

    float *p_hid, *p_bqkv;
    __half *p_xw, *p_qkv, *p_ctx, *p_y, *p_h1;
    __half *p_wqkvT, *p_woT, *p_w1T, *p_w2T;
    cudaGetSymbolAddress((void**)&p_hid,   g_hid);
    cudaGetSymbolAddress((void**)&p_bqkv,  g_bqkv);
    cudaGetSymbolAddress((void**)&p_xw,    h_xw);
    cudaGetSymbolAddress((void**)&p_qkv,   h_qkv);
    cudaGetSymbolAddress((void**)&p_ctx,   h_ctx);
    cudaGetSymbolAddress((void**)&p_y,     h_y);
    cudaGetSymbolAddress((void**)&p_h1,    h_h1);
    cudaGetSymbolAddress((void**)&p_wqkvT, h_wqkvT);
    cudaGetSymbolAddress((void**)&p_woT,   h_woT);
    cudaGetSymbolAddress((void**)&p_w1T,   h_w1T);
    cudaGetSymbolAddress((void**)&p_w2T,   h_w2T);

    cudaFuncSetAttribute(gemm_tc, cudaFuncAttributeMaxDynamicSharedMemorySize, SMEM_TOT);

    const float qscale = 0.17677669529663689f;  // 1/sqrt(32)

    // 0. all weight transposes in one launch + bias concat
    dim3 tb(32, 8);
    transp_all<<<3072, tb>>>(wq, wk, wv, wo, w1, w2,
                             p_wqkvT, p_woT, p_w1T, p_w2T, qscale);
    bias_cat_kernel<<<6, 256>>>(bq, bk, bv, p_bqkv, qscale);

    // 1. LN1 + shift + window partition (fp16)
    ln_kernel<<<T_TOK, 128>>>(x, ln1_g, ln1_b, p_xw, 1);

    // 2. fused QKV projection (fp16 out)
    dim3 gqkv(T_TOK / 128, QKVD / 128);
    gemm_tc<<<gqkv, 256, SMEM_TOT>>>(p_xw, p_wqkvT, p_bqkv, nullptr, p_qkv, C_DIM, QKVD, 0);

    // 3. tensor-core windowed attention
    attn_tc<<<512 * 8, 256>>>(p_qkv, relt, p_ctx);

    // 4. output proj + window reverse + residual (fp32)
    dim3 g4(T_TOK / 128, C_DIM / 128);
    gemm_tc<<<g4, 256, SMEM_TOT>>>(p_ctx, p_woT, bo, x, p_hid, C_DIM, C_DIM, 1);

    // 5. LN2 (fp16 out)
    ln_kernel<<<T_TOK, 128>>>(p_hid, ln2_g, ln2_b, p_y, 0);

    // 6. MLP fc1 + GELU (fp16 out)
    dim3 g16(T_TOK / 128, MLPD / 128);
    gemm_tc<<<g16, 256, SMEM_TOT>>>(p_y, p_w1T, b1, nullptr, p_h1, C_DIM, MLPD, 2);

    // 7. MLP fc2 + residual -> out (fp32)
    gemm_tc<<<g4, 256, SMEM_TOT>>>(p_h1, p_w2T, b2, p_hid, out, MLPD, C_DIM, 3);
}

// round 15
// speedup vs baseline: 1.5026x; 1.0573x over previous
#include <cuda_runtime.h>
#include <cuda_fp16.h>
#include <cstdint>

// ---------------------------------------------------------------------------
// Swin block on GB300 (sm_103 plain target): fp16 mma.sync GEMMs (128x128 CTA
// tile, 8 warps of 64x32, k-chunk 32, 4-stage cp.async, single-barrier
// mainloop unrolled by 4, 2 CTAs/SM); tensor-core windowed attention;
// fp32 LN/residual spine.
// ---------------------------------------------------------------------------

#define T_TOK   32768
#define C_DIM   512
#define QKVD    1536
#define MLPD    2048
#define HEADS_N 16

// ------------------------------- scratch -----------------------------------
__device__ float g_hid[(size_t)T_TOK * C_DIM];
__device__ float g_bqkv[QKVD];
__device__ __half h_xw  [(size_t)T_TOK * C_DIM];
__device__ __half h_qkv [(size_t)T_TOK * QKVD];
__device__ __half h_ctx [(size_t)T_TOK * C_DIM];
__device__ __half h_y   [(size_t)T_TOK * C_DIM];
__device__ __half h_h1  [(size_t)T_TOK * MLPD];
__device__ __half h_wqkvT[(size_t)QKVD * C_DIM];
__device__ __half h_woT [(size_t)C_DIM * C_DIM];
__device__ __half h_w1T [(size_t)MLPD * C_DIM];
__device__ __half h_w2T [(size_t)C_DIM * MLPD];

// ------------------------------- helpers -----------------------------------
__device__ __forceinline__ uint32_t smem_u32(const void* p) {
    uint32_t a;
    asm("{ .reg .u64 t; cvta.to.shared.u64 t, %1; cvt.u32.u64 %0, t; }"
        : "=r"(a) : "l"(p));
    return a;
}
__device__ __forceinline__ void cp_async16(uint32_t dst, const void* src) {
    asm volatile("cp.async.cg.shared.global [%0], [%1], 16;" :: "r"(dst), "l"(src));
}
__device__ __forceinline__ void cp_commit() { asm volatile("cp.async.commit_group;"); }
__device__ __forceinline__ void cp_wait2()  { asm volatile("cp.async.wait_group 2;" ::: "memory"); }

__device__ __forceinline__ void ldm_x4(uint32_t* r, uint32_t addr) {
    asm volatile("ldmatrix.sync.aligned.m8n8.x4.shared.b16 {%0,%1,%2,%3}, [%4];"
                 : "=r"(r[0]), "=r"(r[1]), "=r"(r[2]), "=r"(r[3]) : "r"(addr));
}
__device__ __forceinline__ void ldm_x4t(uint32_t* r, uint32_t addr) {
    asm volatile("ldmatrix.sync.aligned.m8n8.x4.trans.shared.b16 {%0,%1,%2,%3}, [%4];"
                 : "=r"(r[0]), "=r"(r[1]), "=r"(r[2]), "=r"(r[3]) : "r"(addr));
}
__device__ __forceinline__ void mma_f16(float* c, const uint32_t* a, const uint32_t* b) {
    asm volatile("mma.sync.aligned.m16n8k16.row.col.f32.f16.f16.f32 "
                 "{%0,%1,%2,%3}, {%4,%5,%6,%7}, {%8,%9}, {%0,%1,%2,%3};"
                 : "+f"(c[0]), "+f"(c[1]), "+f"(c[2]), "+f"(c[3])
                 : "r"(a[0]), "r"(a[1]), "r"(a[2]), "r"(a[3]), "r"(b[0]), "r"(b[1]));
}

// ---------------- fused weight transpose + fp32->fp16 (+scale) -------------
__global__ void transp_all(const float* __restrict__ wq, const float* __restrict__ wk,
                           const float* __restrict__ wv, const float* __restrict__ wo,
                           const float* __restrict__ w1, const float* __restrict__ w2,
                           __half* __restrict__ wqkvT, __half* __restrict__ woT,
                           __half* __restrict__ w1T, __half* __restrict__ w2T,
                           float qscale)
{
    int t = blockIdx.x;
    const float* W; __half* Wt; int K, N, tx, tloc; float scale = 1.0f;
    if (t < 1024) {
        K = 512; N = 512; tx = 16;
        tloc = t & 255;
        int seg = t >> 8;
        if (seg == 0)      { W = wq; Wt = wqkvT;               scale = qscale; }
        else if (seg == 1) { W = wk; Wt = wqkvT + 512 * 512; }
        else if (seg == 2) { W = wv; Wt = wqkvT + 1024 * 512; }
        else               { W = wo; Wt = woT; }
    } else if (t < 2048) {
        W = w1; Wt = w1T; K = 512; N = 2048; tx = 64; tloc = t - 1024;
    } else {
        W = w2; Wt = w2T; K = 2048; N = 512; tx = 16; tloc = t - 2048;
    }
    int n0 = (tloc % tx) * 32, k0 = (tloc / tx) * 32;

    __shared__ float tbuf[32][33];
    int x = threadIdx.x, y = threadIdx.y;   // 32 x 8
    #pragma unroll
    for (int i = 0; i < 32; i += 8)
        tbuf[y + i][x] = W[(size_t)(k0 + y + i) * N + n0 + x];
    __syncthreads();
    #pragma unroll
    for (int i = 0; i < 32; i += 8)
        Wt[(size_t)(n0 + y + i) * K + k0 + x] = __float2half(tbuf[x][y + i] * scale);
}

__global__ void bias_cat_kernel(const float* __restrict__ bq, const float* __restrict__ bk,
                                const float* __restrict__ bv, float* __restrict__ bqkv,
                                float qscale)
{
    int i = blockIdx.x * 256 + threadIdx.x;
    if (i < 512)       bqkv[i] = bq[i] * qscale;
    else if (i < 1024) bqkv[i] = bk[i - 512];
    else               bqkv[i] = bv[i - 1024];
}

// ----------------------- LayerNorm (+permute), fp16 out --------------------
__global__ void ln_kernel(const float* __restrict__ x,
                          const float* __restrict__ g,
                          const float* __restrict__ b,
                          __half* __restrict__ out, int permute)
{
    int t = blockIdx.x;
    int src = t;
    if (permute) {
        int bb  = t >> 12;
        int win = (t >> 6) & 63;
        int n   = t & 63;
        int hs  = ((win >> 3) << 3) + (n >> 3);
        int ws  = ((win & 7) << 3) + (n & 7);
        int h   = (hs + 4) & 63;
        int w   = (ws + 4) & 63;
        src = (bb << 12) + (h << 6) + w;
    }
    int tid = threadIdx.x;  // 128
    float4 val = ((const float4*)(x + (size_t)src * C_DIM))[tid];
    float s  = val.x + val.y + val.z + val.w;
    float s2 = val.x*val.x + val.y*val.y + val.z*val.z + val.w*val.w;
    #pragma unroll
    for (int o = 16; o; o >>= 1) {
        s  += __shfl_xor_sync(0xffffffffu, s,  o);
        s2 += __shfl_xor_sync(0xffffffffu, s2, o);
    }
    __shared__ float sb[4], s2b[4];
    int warp = tid >> 5, lane = tid & 31;
    if (lane == 0) { sb[warp] = s; s2b[warp] = s2; }
    __syncthreads();
    s  = sb[0] + sb[1] + sb[2] + sb[3];
    s2 = s2b[0] + s2b[1] + s2b[2] + s2b[3];
    float mean = s * (1.0f / C_DIM);
    float var  = s2 * (1.0f / C_DIM) - mean * mean;
    float inv  = rsqrtf(var + 1e-5f);
    float4 gg  = ((const float4*)g)[tid];
    float4 bb4 = ((const float4*)b)[tid];
    float o0 = (val.x - mean) * inv * gg.x + bb4.x;
    float o1 = (val.y - mean) * inv * gg.y + bb4.y;
    float o2 = (val.z - mean) * inv * gg.z + bb4.z;
    float o3 = (val.w - mean) * inv * gg.w + bb4.w;
    __half2 p0 = __floats2half2_rn(o0, o1);
    __half2 p1 = __floats2half2_rn(o2, o3);
    __half2* op = (__half2*)(out + (size_t)t * C_DIM) + 2 * tid;
    op[0] = p0; op[1] = p1;
}

// ------------------------- fp16 mma.sync GEMM ------------------------------
// C[M, Nt] = epi( A[M,K]fp16 @ Bt[Nt,K]fp16^T + bias )
// mode 0: fp16 out   mode 1: fp32 permuted row + res
// mode 2: fp16 GELU  mode 3: fp32 + res
// CTA tile 128x128, 256 threads (8 warps of 64x32), k-chunk 32, 4-stage
// cp.async, single __syncthreads per chunk, mainloop unrolled by 4 so all
// stage offsets are compile-time constants. 2 CTAs/SM. NC must be mult of 4.

#define STAGES 4
#define ROWB   80
#define A_SZ   (128 * ROWB)             // 10240
#define STG_B  (2 * 128 * ROWB)         // 20480 per stage
#define SMEM_TOT (STAGES * STG_B)       // 81920 (x2 CTAs = 163840)

__global__ __launch_bounds__(256, 2)
void gemm_tc(const __half* __restrict__ A, const __half* __restrict__ Bt,
             const float* __restrict__ bias, const float* __restrict__ res,
             void* __restrict__ outp, int K, int Nt, int mode)
{
    extern __shared__ char smem[];
    const uint32_t su = smem_u32(smem);
    const int tid = threadIdx.x, wid = tid >> 5, lane = tid & 31;
    const int m0 = blockIdx.x * 128, n0 = blockIdx.y * 128;
    const int wm0 = (wid & 1) * 64, wn0 = (wid >> 1) * 32;

    // load slots: 2x16B A, 2x16B B per thread (row = idx>>2, chunk = idx&3)
    const char* aG[2]; const char* bG[2];
    uint32_t aS[2], bS[2];
    #pragma unroll
    for (int j = 0; j < 2; j++) {
        int idx = tid + j * 256;
        int r = idx >> 2, c = idx & 3;
        aG[j] = (const char*)(A  + (size_t)(m0 + r) * K + c * 8);
        bG[j] = (const char*)(Bt + (size_t)(n0 + r) * K + c * 8);
        aS[j] = su + r * ROWB + c * 16;
        bS[j] = su + A_SZ + r * ROWB + c * 16;
    }

    const int NC = K >> 5;   // multiple of 4 for K in {512, 2048}

    #pragma unroll
    for (int s = 0; s < STAGES - 1; s++) {
        int koff = s * 64;
        #pragma unroll
        for (int j = 0; j < 2; j++) {
            cp_async16(aS[j] + s * STG_B, aG[j] + koff);
            cp_async16(bS[j] + s * STG_B, bG[j] + koff);
        }
        cp_commit();
    }

    float acc[4][4][4];
    #pragma unroll
    for (int mt = 0; mt < 4; mt++)
        #pragma unroll
        for (int nt = 0; nt < 4; nt++)
            #pragma unroll
            for (int i = 0; i < 4; i++) acc[mt][nt][i] = 0.0f;

    uint32_t aRow = (lane & 7) + ((lane >> 3) & 1) * 8;
    uint32_t aKof = (lane >> 4) * 16;
    uint32_t aBase = su + (wm0 + aRow) * ROWB + aKof;
    uint32_t bRow = (lane & 7) + ((lane >> 4)) * 8;
    uint32_t bKof = ((lane >> 3) & 1) * 16;
    uint32_t bBase = su + A_SZ + (wn0 + bRow) * ROWB + bKof;

    // mainloop unrolled by STAGES: stage index is compile-time constant.
    for (int ch = 0; ch < NC; ch += STAGES) {
        #pragma unroll
        for (int s = 0; s < STAGES; s++) {
            const int wst = (s + STAGES - 1) & (STAGES - 1);  // constant
            cp_wait2();
            __syncthreads();

            // issue loads for chunk ch+s+3 into stage wst (overlap w/ compute)
            int nx = ch + s + STAGES - 1;
            if (nx < NC) {
                int koff = nx * 64;
                #pragma unroll
                for (int j = 0; j < 2; j++) {
                    cp_async16(aS[j] + wst * STG_B, aG[j] + koff);
                    cp_async16(bS[j] + wst * STG_B, bG[j] + koff);
                }
            }
            cp_commit();

            uint32_t aStage = aBase + s * STG_B;   // constant offset
            uint32_t bStage = bBase + s * STG_B;
            #pragma unroll
            for (int k16 = 0; k16 < 2; k16++) {
                uint32_t bf[2][4];
                ldm_x4(bf[0], bStage + k16 * 32);
                ldm_x4(bf[1], bStage + 16 * ROWB + k16 * 32);
                #pragma unroll
                for (int mt = 0; mt < 4; mt++) {
                    uint32_t af[4];
                    ldm_x4(af, aStage + mt * 16 * ROWB + k16 * 32);
                    #pragma unroll
                    for (int nt = 0; nt < 4; nt++)
                        mma_f16(acc[mt][nt], af, &bf[nt >> 1][(nt & 1) * 2]);
                }
            }
        }
    }

    // epilogue
    int rl = lane >> 2, c2 = (lane & 3) * 2;
    #pragma unroll
    for (int mt = 0; mt < 4; mt++) {
        int rows[2] = { m0 + wm0 + mt * 16 + rl, m0 + wm0 + mt * 16 + rl + 8 };
        int orows[2] = { rows[0], rows[1] };
        if (mode == 1) {
            #pragma unroll
            for (int h = 0; h < 2; h++) {
                int row = rows[h];
                int bb  = row >> 12;
                int win = (row >> 6) & 63;
                int n   = row & 63;
                int hs  = ((win >> 3) << 3) + (n >> 3);
                int ws  = ((win & 7) << 3) + (n & 7);
                int hh  = (hs + 4) & 63;
                int ww  = (ws + 4) & 63;
                orows[h] = (bb << 12) + (hh << 6) + ww;
            }
        }
        #pragma unroll
        for (int nt = 0; nt < 4; nt++) {
            int col = n0 + wn0 + nt * 8 + c2;
            float bia0 = bias[col], bia1 = bias[col + 1];
            #pragma unroll
            for (int h = 0; h < 2; h++) {
                float v0 = acc[mt][nt][h * 2]     + bia0;
                float v1 = acc[mt][nt][h * 2 + 1] + bia1;
                size_t rb = (size_t)orows[h] * Nt + col;
                if (mode == 0) {
                    *(__half2*)((__half*)outp + rb) = __floats2half2_rn(v0, v1);
                } else if (mode == 2) {
                    v0 = 0.5f * v0 * (1.0f + erff(v0 * 0.70710678118654752f));
                    v1 = 0.5f * v1 * (1.0f + erff(v1 * 0.70710678118654752f));
                    *(__half2*)((__half*)outp + rb) = __floats2half2_rn(v0, v1);
                } else {
                    float2 r2 = *(const float2*)(res + rb);
                    float2 o2; o2.x = v0 + r2.x; o2.y = v1 + r2.y;
                    *(float2*)((float*)outp + rb) = o2;
                }
            }
        }
    }
}

// ------------------- tensor-core windowed attention ------------------------
#define APITCH 80   // bytes per 32-dim row (64 data + 16 pad)

__global__ __launch_bounds__(256)
void attn_tc(const __half* __restrict__ qkv,
             const float* __restrict__ bias_table,
             __half* __restrict__ ctx)
{
    int blk = blockIdx.x;           // 512 * 8
    int w  = blk >> 3;
    int hp = blk & 7;
    int tid = threadIdx.x, wid = tid >> 5, lane = tid & 31;
    int hd  = wid >> 2;
    int hh  = hp * 2 + hd;
    int r0  = (wid & 3) * 16;

    __shared__ __half sm[2 * 3 * 64 * (APITCH / 2)];

    #pragma unroll
    for (int j = 0; j < 6; j++) {
        int idx = tid + j * 256;
        int head = idx / 768;
        int rem  = idx - head * 768;
        int te   = rem >> 8;
        int r2   = rem & 255;
        int row  = r2 >> 2;
        int chk  = r2 & 3;
        const uint4* src = (const uint4*)(qkv + (size_t)(w * 64 + row) * QKVD
                                          + te * 512 + (hp * 2 + head) * 32 + chk * 8);
        uint4* dst = (uint4*)(sm + ((head * 3 + te) * 64 + row) * 40 + chk * 8);
        *dst = *src;
    }
    __syncthreads();

    uint32_t smb = smem_u32(sm);
    uint32_t qB = smb + (hd * 3 + 0) * 64 * APITCH;
    uint32_t kB = smb + (hd * 3 + 1) * 64 * APITCH;
    uint32_t vB = smb + (hd * 3 + 2) * 64 * APITCH;

    float sacc[8][4];
    #pragma unroll
    for (int nt = 0; nt < 8; nt++)
        #pragma unroll
        for (int i = 0; i < 4; i++) sacc[nt][i] = 0.0f;

    uint32_t aRow = r0 + (lane & 7) + ((lane >> 3) & 1) * 8;
    uint32_t aKof = (lane >> 4) * 16;
    uint32_t bRowB = (lane & 7) + (lane >> 4) * 8;
    uint32_t bKof = ((lane >> 3) & 1) * 16;

    #pragma unroll
    for (int k16 = 0; k16 < 2; k16++) {
        uint32_t af[4];
        ldm_x4(af, qB + aRow * APITCH + aKof + k16 * 32);
        #pragma unroll
        for (int g = 0; g < 4; g++) {
            uint32_t bf[4];
            ldm_x4(bf, kB + (g * 16 + bRowB) * APITCH + bKof + k16 * 32);
            mma_f16(sacc[2 * g],     af, &bf[0]);
            mma_f16(sacc[2 * g + 1], af, &bf[2]);
        }
    }

    int win = w & 63;
    int wh = win >> 3, ww = win & 7;
    int ra = r0 + (lane >> 2);
    int cbase = (lane & 3) * 2;
    #pragma unroll
    for (int hrow = 0; hrow < 2; hrow++) {
        int r = ra + hrow * 8;
        int i1 = r >> 3, j1 = r & 7;
        int hs1 = wh * 8 + i1, ws1 = ww * 8 + j1;
        int reg1 = (hs1 < 56 ? 0 : (hs1 < 60 ? 1 : 2)) * 3 + (ws1 < 56 ? 0 : (ws1 < 60 ? 1 : 2));
        #pragma unroll
        for (int nt = 0; nt < 8; nt++) {
            #pragma unroll
            for (int cc = 0; cc < 2; cc++) {
                int col = nt * 8 + cbase + cc;
                int j2 = col & 7;
                int rel = (i1 - nt + 7) * 15 + (j1 - j2 + 7);
                float s = sacc[nt][hrow * 2 + cc] + bias_table[rel * HEADS_N + hh];
                int hs2 = wh * 8 + nt, ws2 = ww * 8 + j2;
                int reg2 = (hs2 < 56 ? 0 : (hs2 < 60 ? 1 : 2)) * 3 + (ws2 < 56 ? 0 : (ws2 < 60 ? 1 : 2));
                if (reg1 != reg2) s -= 100.0f;
                sacc[nt][hrow * 2 + cc] = s;
            }
        }
    }

    #pragma unroll
    for (int hrow = 0; hrow < 2; hrow++) {
        float mx = -1e30f;
        #pragma unroll
        for (int nt = 0; nt < 8; nt++)
            mx = fmaxf(mx, fmaxf(sacc[nt][hrow * 2], sacc[nt][hrow * 2 + 1]));
        mx = fmaxf(mx, __shfl_xor_sync(0xffffffffu, mx, 1));
        mx = fmaxf(mx, __shfl_xor_sync(0xffffffffu, mx, 2));
        float sum = 0.0f;
        #pragma unroll
        for (int nt = 0; nt < 8; nt++) {
            float e0 = expf(sacc[nt][hrow * 2]     - mx);
            float e1 = expf(sacc[nt][hrow * 2 + 1] - mx);
            sacc[nt][hrow * 2] = e0; sacc[nt][hrow * 2 + 1] = e1;
            sum += e0 + e1;
        }
        sum += __shfl_xor_sync(0xffffffffu, sum, 1);
        sum += __shfl_xor_sync(0xffffffffu, sum, 2);
        float inv = 1.0f / sum;
        #pragma unroll
        for (int nt = 0; nt < 8; nt++) {
            sacc[nt][hrow * 2]     *= inv;
            sacc[nt][hrow * 2 + 1] *= inv;
        }
    }

    uint32_t pa[4][4];
    #pragma unroll
    for (int ks = 0; ks < 4; ks++) {
        __half2 t0 = __floats2half2_rn(sacc[2 * ks][0],     sacc[2 * ks][1]);
        __half2 t1 = __floats2half2_rn(sacc[2 * ks][2],     sacc[2 * ks][3]);
        __half2 t2 = __floats2half2_rn(sacc[2 * ks + 1][0], sacc[2 * ks + 1][1]);
        __half2 t3 = __floats2half2_rn(sacc[2 * ks + 1][2], sacc[2 * ks + 1][3]);
        pa[ks][0] = *(uint32_t*)&t0; pa[ks][1] = *(uint32_t*)&t1;
        pa[ks][2] = *(uint32_t*)&t2; pa[ks][3] = *(uint32_t*)&t3;
    }

    float oacc[4][4];
    #pragma unroll
    for (int nt = 0; nt < 4; nt++)
        #pragma unroll
        for (int i = 0; i < 4; i++) oacc[nt][i] = 0.0f;

    uint32_t vRow = (lane & 7) + ((lane >> 3) & 1) * 8;
    uint32_t vOff = (lane >> 4) * 16;
    #pragma unroll
    for (int ks = 0; ks < 4; ks++) {
        uint32_t vf0[4], vf1[4];
        uint32_t base = vB + (ks * 16 + vRow) * APITCH;
        ldm_x4t(vf0, base + vOff);
        ldm_x4t(vf1, base + 32 + vOff);
        mma_f16(oacc[0], pa[ks], &vf0[0]);
        mma_f16(oacc[1], pa[ks], &vf0[2]);
        mma_f16(oacc[2], pa[ks], &vf1[0]);
        mma_f16(oacc[3], pa[ks], &vf1[2]);
    }

    #pragma unroll
    for (int hrow = 0; hrow < 2; hrow++) {
        int row = w * 64 + ra + hrow * 8;
        #pragma unroll
        for (int nt = 0; nt < 4; nt++) {
            int col = hh * 32 + nt * 8 + cbase;
            __half2 p = __floats2half2_rn(oacc[nt][hrow * 2], oacc[nt][hrow * 2 + 1]);
            *(__half2*)(ctx + (size_t)row * C_DIM + col) = p;
        }
    }
}

// ------------------------------- launcher ----------------------------------
extern "C" void kernel_launch(void* const* d_in, const int* in_sizes, int n_in,
                              void* d_out, int out_size)
{
    const float* x      = (const float*)d_in[0];
    const float* ln1_g  = (const float*)d_in[1];
    const float* ln1_b  = (const float*)d_in[2];
    const float* wq     = (const float*)d_in[3];
    const float* bq     = (const float*)d_in[4];
    const float* wk     = (const float*)d_in[5];
    const float* bk     = (const float*)d_in[6];
    const float* wv     = (const float*)d_in[7];
    const float* bv     = (const float*)d_in[8];
    const float* relt   = (const float*)d_in[9];
    const float* wo     = (const float*)d_in[10];
    const float* bo     = (const float*)d_in[11];
    const float* ln2_g  = (const float*)d_in[12];
    const float* ln2_b  = (const float*)d_in[13];
    const float* w1     = (const float*)d_in[14];
    const float* b1     = (const float*)d_in[15];
    const float* w2     = (const float*)d_in[16];
    const float* b2     = (const float*)d_in[17];
    float* out          = (float*)d_out;

    float *p_hid, *p_bqkv;
    __half *p_xw, *p_qkv, *p_ctx, *p_y, *p_h1;
    __half *p_wqkvT, *p_woT, *p_w1T, *p_w2T;
    cudaGetSymbolAddress((void**)&p_hid,   g_hid);
    cudaGetSymbolAddress((void**)&p_bqkv,  g_bqkv);
    cudaGetSymbolAddress((void**)&p_xw,    h_xw);
    cudaGetSymbolAddress((void**)&p_qkv,   h_qkv);
    cudaGetSymbolAddress((void**)&p_ctx,   h_ctx);
    cudaGetSymbolAddress((void**)&p_y,     h_y);
    cudaGetSymbolAddress((void**)&p_h1,    h_h1);
    cudaGetSymbolAddress((void**)&p_wqkvT, h_wqkvT);
    cudaGetSymbolAddress((void**)&p_woT,   h_woT);
    cudaGetSymbolAddress((void**)&p_w1T,   h_w1T);
    cudaGetSymbolAddress((void**)&p_w2T,   h_w2T);

    cudaFuncSetAttribute(gemm_tc, cudaFuncAttributeMaxDynamicSharedMemorySize, SMEM_TOT);

    const float qscale = 0.17677669529663689f;  // 1/sqrt(32)

    // 0. all weight transposes in one launch + bias concat
    dim3 tb(32, 8);
    transp_all<<<3072, tb>>>(wq, wk, wv, wo, w1, w2,
                             p_wqkvT, p_woT, p_w1T, p_w2T, qscale);
    bias_cat_kernel<<<6, 256>>>(bq, bk, bv, p_bqkv, qscale);

    // 1. LN1 + shift + window partition (fp16)
    ln_kernel<<<T_TOK, 128>>>(x, ln1_g, ln1_b, p_xw, 1);

    // 2. fused QKV projection (fp16 out)
    dim3 gqkv(T_TOK / 128, QKVD / 128);
    gemm_tc<<<gqkv, 256, SMEM_TOT>>>(p_xw, p_wqkvT, p_bqkv, nullptr, p_qkv, C_DIM, QKVD, 0);

    // 3. tensor-core windowed attention
    attn_tc<<<512 * 8, 256>>>(p_qkv, relt, p_ctx);

    // 4. output proj + window reverse + residual (fp32)
    dim3 g4(T_TOK / 128, C_DIM / 128);
    gemm_tc<<<g4, 256, SMEM_TOT>>>(p_ctx, p_woT, bo, x, p_hid, C_DIM, C_DIM, 1);

    // 5. LN2 (fp16 out)
    ln_kernel<<<T_TOK, 128>>>(p_hid, ln2_g, ln2_b, p_y, 0);

    // 6. MLP fc1 + GELU (fp16 out)
    dim3 g16(T_TOK / 128, MLPD / 128);
    gemm_tc<<<g16, 256, SMEM_TOT>>>(p_y, p_w1T, b1, nullptr, p_h1, C_DIM, MLPD, 2);

    // 7. MLP fc2 + residual -> out (fp32)
    gemm_tc<<<g4, 256, SMEM_TOT>>>(p_h1, p_w2T, b2, p_hid, out, MLPD, C_DIM, 3);
}